// round 16
// baseline (speedup 1.0000x reference)
#include <cuda_runtime.h>
#include <cstdint>

// SNNQNet bit-exact scalar path, round 11: t-split GEMM (two passes of 4
// timesteps) -> 32-reg accumulators -> __launch_bounds__(256,3) -> 24 warps/SM.
// LIF membrane checkpoints at t=3 (8 floats carried across passes).
// Nibble LUT (512B) + nibble-level skips in hidden layers.
// Same adds, same k-ascending order per (h,t) => membranes bit-identical
// (rel_err 9.000283e-8).

constexpr int Bn = 16384;
constexpr int Sn = 256;
constexpr int Hn = 128;
constexpr int An = 18;
constexpr int Tn = 8;

constexpr int BLOCK = 256;       // 8 warps
constexpr int RPB   = 16;        // batch rows per block (2 per warp)
constexpr int GRID  = Bn / RPB;  // 1024

typedef unsigned long long ull;
typedef unsigned short u16;

// Pre-paired weights: [k][lane] = { pk(W[k][lane],W[k][lane+64]),
//                                   pk(W[k][lane+32],W[k][lane+96]) }
__device__ __align__(256) ulonglong2 g_Wpk_in[Sn * 32];
__device__ __align__(256) ulonglong2 g_Wpk_r1[Hn * 32];
__device__ __align__(256) ulonglong2 g_Wpk_r2[Hn * 32];

__device__ __forceinline__ ull pk(float a, float b) {
    return (ull)__float_as_uint(a) | ((ull)__float_as_uint(b) << 32);
}

__global__ void pack_kernel(const float* __restrict__ W, ulonglong2* __restrict__ dst,
                            int K) {
    int i = blockIdx.x * 256 + threadIdx.x;
    if (i >= K * 32) return;
    int k = i >> 5, lane = i & 31;
    const float* wr = W + k * Hn;
    dst[i] = make_ulonglong2(pk(wr[lane], wr[lane + 64]),
                             pk(wr[lane + 32], wr[lane + 96]));
}

__device__ __forceinline__ float f2lo(ull v) { return __uint_as_float((unsigned)v); }
__device__ __forceinline__ float f2hi(ull v) { return __uint_as_float((unsigned)(v >> 32)); }

__device__ __forceinline__ void fmad2(ull& u, ull w, ull s) {
    asm("fma.rn.f32x2 %0, %1, %2, %0;" : "+l"(u) : "l"(w), "l"(s));
}

// One t-group GEMM pass (4 timesteps) for the warp's 2 rows.
// Accumulators: A0/A1 (row A, h-pairs lo/hi), B0/B1 (row B), 4 t's each.
template <int K, bool SKIP>
__device__ __forceinline__ void gemm_t(const ulonglong2* __restrict__ wg,
                                       const u16* __restrict__ sp,
                                       const ull* __restrict__ lutn, int lane,
                                       int grp, ull* A0, ull* A1, ull* B0, ull* B1) {
    const ulonglong2* wk = wg + lane;
    const unsigned gsh = grp * 4;
    const ull gmask = 0x0F0F0F0F0F0F0F0FULL << gsh;
#pragma unroll 1
    for (int k4 = 0; k4 < K; k4 += 4) {
        ull b4 = *(const ull*)(sp + k4);  // 4 k's of row-pair bytes
        if (SKIP && (b4 & gmask) == 0ull) continue;
#pragma unroll
        for (int j = 0; j < 4; j++) {
            unsigned pr = (unsigned)(b4 >> (16 * j)) & 0xFFFFu;
            unsigned na = (pr >> gsh) & 0xFu;        // row A nibble (this t-group)
            unsigned nb = (pr >> (8 + gsh)) & 0xFu;  // row B nibble
            if (SKIP && (na | nb) == 0u) continue;
            ulonglong2 w = __ldg(wk + (k4 + j) * 32);
            if (!SKIP || na) {
                const ulonglong2* lp = (const ulonglong2*)(lutn + na * 4);
                ulonglong2 s01 = lp[0], s23 = lp[1];
                fmad2(A0[0], w.x, s01.x); fmad2(A1[0], w.y, s01.x);
                fmad2(A0[1], w.x, s01.y); fmad2(A1[1], w.y, s01.y);
                fmad2(A0[2], w.x, s23.x); fmad2(A1[2], w.y, s23.x);
                fmad2(A0[3], w.x, s23.y); fmad2(A1[3], w.y, s23.y);
            }
            if (!SKIP || nb) {
                const ulonglong2* lp = (const ulonglong2*)(lutn + nb * 4);
                ulonglong2 s01 = lp[0], s23 = lp[1];
                fmad2(B0[0], w.x, s01.x); fmad2(B1[0], w.y, s01.x);
                fmad2(B0[1], w.x, s01.y); fmad2(B1[1], w.y, s01.y);
                fmad2(B0[2], w.x, s23.x); fmad2(B1[2], w.y, s23.x);
                fmad2(B0[3], w.x, s23.y); fmad2(B1[3], w.y, s23.y);
            }
        }
    }
}

// Butterfly-reduce 4 floats across the warp.
__device__ __forceinline__ void wred4(float* p) {
#pragma unroll
    for (int off = 16; off > 0; off >>= 1) {
#pragma unroll
        for (int t = 0; t < 4; t++)
            p[t] += __shfl_xor_sync(0xffffffffu, p[t], off);
    }
}

// LN + residual + LIF for 4 timesteps (tbase..tbase+3) of one row.
// v[4] and n[4] carry membrane + spike bits across t-groups.
__device__ __forceinline__ void ln_lif_half(const ull* u0, const ull* u1,
                                            const float* cb, unsigned q0, unsigned q1,
                                            unsigned q2, unsigned q3, int lane,
                                            int tbase, float* v, unsigned* n) {
    float p[4];
#pragma unroll
    for (int tl = 0; tl < 4; tl++)
        p[tl] = f2lo(u0[tl]) + f2hi(u0[tl]) + f2lo(u1[tl]) + f2hi(u1[tl]);
    wred4(p);
    float mu[4];
#pragma unroll
    for (int tl = 0; tl < 4; tl++) mu[tl] = p[tl] * (1.0f / 128.0f);
#pragma unroll
    for (int tl = 0; tl < 4; tl++) {
        float a = f2lo(u0[tl]) - mu[tl];
        float b = f2hi(u0[tl]) - mu[tl];
        float c = f2lo(u1[tl]) - mu[tl];
        float d = f2hi(u1[tl]) - mu[tl];
        p[tl] = a * a + b * b + c * c + d * d;
    }
    wred4(p);
    const float g0 = cb[128 + lane],      g1 = cb[128 + lane + 64];
    const float g2 = cb[128 + lane + 32], g3 = cb[128 + lane + 96];
    const float e0 = cb[256 + lane],      e1 = cb[256 + lane + 64];
    const float e2 = cb[256 + lane + 32], e3 = cb[256 + lane + 96];
#pragma unroll
    for (int tl = 0; tl < 4; tl++) {
        const int t = tbase + tl;
        float rs = rsqrtf(p[tl] * (1.0f / 128.0f) + 1e-5f);
        float y0 = (f2lo(u0[tl]) - mu[tl]) * rs * g0 + e0 + (float)((q0 >> t) & 1);
        float y1 = (f2hi(u0[tl]) - mu[tl]) * rs * g1 + e1 + (float)((q1 >> t) & 1);
        float y2 = (f2lo(u1[tl]) - mu[tl]) * rs * g2 + e2 + (float)((q2 >> t) & 1);
        float y3 = (f2hi(u1[tl]) - mu[tl]) * rs * g3 + e3 + (float)((q3 >> t) & 1);
        v[0] += (y0 - v[0]) * 0.5f; if (v[0] >= 1.f) { n[0] |= 1u << t; v[0] = 0.f; }
        v[1] += (y1 - v[1]) * 0.5f; if (v[1] >= 1.f) { n[1] |= 1u << t; v[1] = 0.f; }
        v[2] += (y2 - v[2]) * 0.5f; if (v[2] >= 1.f) { n[2] |= 1u << t; v[2] = 0.f; }
        v[3] += (y3 - v[3]) * 0.5f; if (v[3] >= 1.f) { n[3] |= 1u << t; v[3] = 0.f; }
    }
}

// Plain LIF for 4 timesteps (phase 1, no LN/residual).
__device__ __forceinline__ void lif_half(const ull* u0, const ull* u1, int tbase,
                                         float* v, unsigned* n) {
#pragma unroll
    for (int tl = 0; tl < 4; tl++) {
        const int t = tbase + tl;
        float a = f2lo(u0[tl]), b = f2hi(u0[tl]);
        float c = f2lo(u1[tl]), d = f2hi(u1[tl]);
        v[0] += (a - v[0]) * 0.5f; if (v[0] >= 1.f) { n[0] |= 1u << t; v[0] = 0.f; }
        v[1] += (b - v[1]) * 0.5f; if (v[1] >= 1.f) { n[1] |= 1u << t; v[1] = 0.f; }
        v[2] += (c - v[2]) * 0.5f; if (v[2] >= 1.f) { n[2] |= 1u << t; v[2] = 0.f; }
        v[3] += (d - v[3]) * 0.5f; if (v[3] >= 1.f) { n[3] |= 1u << t; v[3] = 0.f; }
    }
}

__device__ __forceinline__ void store_pair(u16* hout, int warp, int lane,
                                           const unsigned* nA, const unsigned* nB) {
    u16* hp = hout + warp * Hn;
    hp[lane]      = (u16)(nA[0] | (nB[0] << 8));
    hp[lane + 64] = (u16)(nA[1] | (nB[1] << 8));
    hp[lane + 32] = (u16)(nA[2] | (nB[2] << 8));
    hp[lane + 96] = (u16)(nA[3] | (nB[3] << 8));
}

// One MS_ResBlock for the warp's row pair, t-split into two passes.
__device__ __forceinline__ void resblock_ts(const ulonglong2* __restrict__ wg,
                                            const float* __restrict__ cb,
                                            const ull* __restrict__ lutn,
                                            const u16* __restrict__ hin,
                                            u16* __restrict__ hout, int warp,
                                            int lane) {
    const ull bi0 = pk(cb[lane], cb[lane + 64]);
    const ull bi1 = pk(cb[lane + 32], cb[lane + 96]);
    const u16* hp = hin + warp * Hn;
    const unsigned p0 = hp[lane], p1 = hp[lane + 64];
    const unsigned p2 = hp[lane + 32], p3 = hp[lane + 96];
    float vA[4] = {0, 0, 0, 0}, vB[4] = {0, 0, 0, 0};
    unsigned nA[4] = {0, 0, 0, 0}, nB[4] = {0, 0, 0, 0};
#pragma unroll 1
    for (int g = 0; g < 2; g++) {
        ull A0[4], A1[4], B0[4], B1[4];
#pragma unroll
        for (int tl = 0; tl < 4; tl++) {
            A0[tl] = bi0; A1[tl] = bi1; B0[tl] = bi0; B1[tl] = bi1;
        }
        gemm_t<Hn, true>(wg, hp, lutn, lane, g, A0, A1, B0, B1);
        ln_lif_half(A0, A1, cb, p0 & 0xFFu, p1 & 0xFFu, p2 & 0xFFu, p3 & 0xFFu, lane,
                    g * 4, vA, nA);
        ln_lif_half(B0, B1, cb, p0 >> 8, p1 >> 8, p2 >> 8, p3 >> 8, lane, g * 4, vB,
                    nB);
    }
    store_pair(hout, warp, lane, nA, nB);
    __syncwarp();
}

__global__ __launch_bounds__(BLOCK, 3) void snn_kernel(
    const float* __restrict__ x, const float* __restrict__ enc,
    const float* __restrict__ b_in, const float* __restrict__ b_r1,
    const float* __restrict__ g_r1, const float* __restrict__ be_r1,
    const float* __restrict__ b_r2, const float* __restrict__ g_r2,
    const float* __restrict__ be_r2, const float* __restrict__ W_out,
    const float* __restrict__ b_out, float* __restrict__ out) {
    __shared__ u16 sIN[8 * Sn];
    __shared__ u16 hA[8 * Hn];
    __shared__ u16 hB[8 * Hn];
    __shared__ float wout[Hn * An];
    __shared__ float bout[32];
    __shared__ float cb_in[128];
    __shared__ float cb_r1[384];
    __shared__ float cb_r2[384];
    __shared__ ull lutn[16 * 4];  // nibble LUT: [nib][t_local] = {s,s}

    const int b0 = blockIdx.x * RPB;
    const int tid = threadIdx.x;
    const int warp = tid >> 5;
    const int lane = tid & 31;

    // ---- Phase 0: nibble LUT, encode, constants. One block barrier. ----
    if (tid < 64) {
        int nib = tid >> 2, tl = tid & 3;
        unsigned u = ((nib >> tl) & 1) ? 0x3F800000u : 0u;
        lutn[tid] = ((ull)u << 32) | u;
    }
    for (int i = tid; i < 8 * 64; i += BLOCK) {
        int w = i >> 6;
        int s4 = (i & 63) * 4;
        int bA = b0 + 2 * w, bB = bA + 1;
        float4 xA = *(const float4*)(x + (size_t)bA * Sn + s4);
        float4 xB = *(const float4*)(x + (size_t)bB * Sn + s4);
        unsigned byA0 = 0, byA1 = 0, byA2 = 0, byA3 = 0;
        unsigned byB0 = 0, byB1 = 0, byB2 = 0, byB3 = 0;
#pragma unroll
        for (int t = 0; t < Tn; t++) {
            float4 eA = *(const float4*)(enc + ((size_t)t * Bn + bA) * Sn + s4);
            float4 eB = *(const float4*)(enc + ((size_t)t * Bn + bB) * Sn + s4);
            unsigned bit = 1u << t;
            if (eA.x <= xA.x) byA0 |= bit;
            if (eA.y <= xA.y) byA1 |= bit;
            if (eA.z <= xA.z) byA2 |= bit;
            if (eA.w <= xA.w) byA3 |= bit;
            if (eB.x <= xB.x) byB0 |= bit;
            if (eB.y <= xB.y) byB1 |= bit;
            if (eB.z <= xB.z) byB2 |= bit;
            if (eB.w <= xB.w) byB3 |= bit;
        }
        ull packed = (ull)(byA0 | (byB0 << 8)) | ((ull)(byA1 | (byB1 << 8)) << 16) |
                     ((ull)(byA2 | (byB2 << 8)) << 32) | ((ull)(byA3 | (byB3 << 8)) << 48);
        *(ull*)(sIN + w * Sn + s4) = packed;
    }
    for (int i = tid; i < Hn; i += BLOCK) {
        cb_in[i] = b_in[i];
        cb_r1[i] = b_r1[i]; cb_r1[128 + i] = g_r1[i]; cb_r1[256 + i] = be_r1[i];
        cb_r2[i] = b_r2[i]; cb_r2[128 + i] = g_r2[i]; cb_r2[256 + i] = be_r2[i];
    }
    for (int i = tid; i < Hn * An; i += BLOCK) wout[i] = W_out[i];
    if (tid < An) bout[tid] = b_out[tid];
    __syncthreads();

    // ---- Phase 1: GEMM1 (dense) + LIF, t-split -> hA ----
    {
        const ull bi0 = pk(cb_in[lane], cb_in[lane + 64]);
        const ull bi1 = pk(cb_in[lane + 32], cb_in[lane + 96]);
        float vA[4] = {0, 0, 0, 0}, vB[4] = {0, 0, 0, 0};
        unsigned nA[4] = {0, 0, 0, 0}, nB[4] = {0, 0, 0, 0};
#pragma unroll 1
        for (int g = 0; g < 2; g++) {
            ull A0[4], A1[4], B0[4], B1[4];
#pragma unroll
            for (int tl = 0; tl < 4; tl++) {
                A0[tl] = bi0; A1[tl] = bi1; B0[tl] = bi0; B1[tl] = bi1;
            }
            gemm_t<Sn, false>(g_Wpk_in, sIN + warp * Sn, lutn, lane, g, A0, A1, B0, B1);
            lif_half(A0, A1, g * 4, vA, nA);
            lif_half(B0, B1, g * 4, vB, nB);
        }
        store_pair(hA, warp, lane, nA, nB);
        __syncwarp();
    }

    // ---- Phases 2-3: ResBlocks (warp-independent) ----
    resblock_ts(g_Wpk_r1, cb_r1, lutn, hA, hB, warp, lane);
    resblock_ts(g_Wpk_r2, cb_r2, lutn, hB, hA, warp, lane);
    __syncthreads();

    // ---- Phase 4: readout GEMM (H=128 -> A=18) + non-spiking LIF + time mean ----
    const float WGT[Tn] = {255.f / 2048.f, 127.f / 1024.f, 63.f / 512.f, 31.f / 256.f,
                           15.f / 128.f,   7.f / 64.f,     3.f / 32.f,   1.f / 16.f};
    const unsigned char* hby = (const unsigned char*)hA;
    for (int task = tid; task < RPB * An; task += BLOCK) {
        int r = task / An;
        int a = task - r * An;
        float acc[Tn] = {0.f, 0.f, 0.f, 0.f, 0.f, 0.f, 0.f, 0.f};
        const unsigned char* hp = hby + (r >> 1) * 256 + (r & 1);
        for (int h = 0; h < Hn; h++) {
            unsigned byte = hp[h * 2];
            float w = wout[h * An + a];
#pragma unroll
            for (int t = 0; t < Tn; t++)
                if (byte & (1u << t)) acc[t] += w;
        }
        float bo = bout[a];
        float o = 0.f;
#pragma unroll
        for (int t = 0; t < Tn; t++) o += WGT[t] * (acc[t] + bo);
        out[(size_t)(b0 + r) * An + a] = o;
    }
}

extern "C" void kernel_launch(void* const* d_in, const int* in_sizes, int n_in,
                              void* d_out, int out_size) {
    const float* x     = (const float*)d_in[0];
    const float* enc   = (const float*)d_in[1];
    const float* W_in  = (const float*)d_in[2];
    const float* b_in  = (const float*)d_in[3];
    const float* W_r1  = (const float*)d_in[4];
    const float* b_r1  = (const float*)d_in[5];
    const float* g_r1  = (const float*)d_in[6];
    const float* be_r1 = (const float*)d_in[7];
    const float* W_r2  = (const float*)d_in[8];
    const float* b_r2  = (const float*)d_in[9];
    const float* g_r2  = (const float*)d_in[10];
    const float* be_r2 = (const float*)d_in[11];
    const float* W_out = (const float*)d_in[12];
    const float* b_out = (const float*)d_in[13];
    float* out = (float*)d_out;

    ulonglong2 *Wp_in, *Wp_r1, *Wp_r2;
    cudaGetSymbolAddress((void**)&Wp_in, g_Wpk_in);
    cudaGetSymbolAddress((void**)&Wp_r1, g_Wpk_r1);
    cudaGetSymbolAddress((void**)&Wp_r2, g_Wpk_r2);

    pack_kernel<<<(Sn * 32 + 255) / 256, 256>>>(W_in, Wp_in, Sn);
    pack_kernel<<<(Hn * 32 + 255) / 256, 256>>>(W_r1, Wp_r1, Hn);
    pack_kernel<<<(Hn * 32 + 255) / 256, 256>>>(W_r2, Wp_r2, Hn);
    snn_kernel<<<GRID, BLOCK>>>(x, enc, b_in, b_r1, g_r1, be_r1, b_r2, g_r2, be_r2,
                                W_out, b_out, out);
}

// round 17
// speedup vs baseline: 1.1558x; 1.1558x over previous
#include <cuda_runtime.h>
#include <cstdint>

// SNNQNet bit-exact scalar path, round 12: round-10 champion + branch-free
// hidden-layer GEMM over compacted nonzero-k lists (ballot/popc, ascending k).
// Unconditional row processing per listed k (w*0 = +0 adds are bit-exact).
// Membranes bit-identical to k-ascending fp32 RN adds (rel_err 9.000283e-8).

constexpr int Bn = 16384;
constexpr int Sn = 256;
constexpr int Hn = 128;
constexpr int An = 18;
constexpr int Tn = 8;

constexpr int BLOCK = 256;       // 8 warps
constexpr int RPB   = 16;        // batch rows per block (2 per warp)
constexpr int GRID  = Bn / RPB;  // 1024

typedef unsigned long long ull;
typedef unsigned short u16;
typedef unsigned int u32;

// Pre-paired weights: dst[k*64+j] = { lo: W[k][j], hi: W[k][j+64] }
__device__ __align__(256) ull g_Wpk_in[Sn * 64];
__device__ __align__(256) ull g_Wpk_r1[Hn * 64];
__device__ __align__(256) ull g_Wpk_r2[Hn * 64];

__global__ void pack_kernel(const float* __restrict__ W, ull* __restrict__ dst,
                            int K) {
    int i = blockIdx.x * 256 + threadIdx.x;
    if (i >= K * 64) return;
    int k = i >> 6, j = i & 63;
    dst[i] = ((ull)__float_as_uint(W[k * Hn + j + 64]) << 32) |
             __float_as_uint(W[k * Hn + j]);
}

__device__ __forceinline__ float f2lo(ull v) { return __uint_as_float((unsigned)v); }
__device__ __forceinline__ float f2hi(ull v) { return __uint_as_float((unsigned)(v >> 32)); }
__device__ __forceinline__ ull pk(float a, float b) {
    return (ull)__float_as_uint(a) | ((ull)__float_as_uint(b) << 32);
}

__device__ __forceinline__ void fmad2(ull& u, ull w, ull s) {
    asm("fma.rn.f32x2 %0, %1, %2, %0;" : "+l"(u) : "l"(w), "l"(s));
}

// 16 fma2: 8 timesteps x 2 h-pairs, one k step, one row.
__device__ __forceinline__ void fma8(ull* u0, ull* u1, ull w0, ull w1,
                                     const ulonglong2* __restrict__ lp) {
    ulonglong2 sA = lp[0], sB = lp[1], sC = lp[2], sD = lp[3];
    fmad2(u0[0], w0, sA.x); fmad2(u1[0], w1, sA.x);
    fmad2(u0[1], w0, sA.y); fmad2(u1[1], w1, sA.y);
    fmad2(u0[2], w0, sB.x); fmad2(u1[2], w1, sB.x);
    fmad2(u0[3], w0, sB.y); fmad2(u1[3], w1, sB.y);
    fmad2(u0[4], w0, sC.x); fmad2(u1[4], w1, sC.x);
    fmad2(u0[5], w0, sC.y); fmad2(u1[5], w1, sC.y);
    fmad2(u0[6], w0, sD.x); fmad2(u1[6], w1, sD.x);
    fmad2(u0[7], w0, sD.y); fmad2(u1[7], w1, sD.y);
}

// Dense 2-row GEMM over K (phase 1; spike density 0.5 -> no skips).
template <int K>
__device__ __forceinline__ void gemm_dense(const ull* __restrict__ wg,
                                           const u16* __restrict__ sp,
                                           const ull* __restrict__ lut, int lane,
                                           ull* A0, ull* A1, ull* B0, ull* B1) {
    const ull* wk = wg + lane;
#pragma unroll 1
    for (int k4 = 0; k4 < K; k4 += 4) {
        ull b4 = *(const ull*)(sp + k4);
#pragma unroll
        for (int j = 0; j < 4; j++) {
            unsigned pr = (unsigned)(b4 >> (16 * j)) & 0xFFFFu;
            ull w0 = __ldg(wk + (k4 + j) * 64);
            ull w1 = __ldg(wk + (k4 + j) * 64 + 32);
            fma8(A0, A1, w0, w1, (const ulonglong2*)(lut + (pr & 0xFFu) * 8));
            fma8(B0, B1, w0, w1, (const ulonglong2*)(lut + (pr >> 8) * 8));
        }
    }
}

// Branch-free sparse GEMM over a compacted list of (k | pr<<16) entries,
// ascending k. Both rows processed unconditionally (w*0 adds are +0 = exact).
__device__ __forceinline__ void gemm_list(const ull* __restrict__ wg,
                                          const u32* __restrict__ list, int nnz,
                                          const ull* __restrict__ lut, int lane,
                                          ull* A0, ull* A1, ull* B0, ull* B1) {
    const ull* wk = wg + lane;
#pragma unroll 2
    for (int i = 0; i < nnz; i++) {
        u32 e = list[i];
        int k = e & 0xFFFFu;
        unsigned pr = e >> 16;
        ull w0 = __ldg(wk + k * 64);
        ull w1 = __ldg(wk + k * 64 + 32);
        fma8(A0, A1, w0, w1, (const ulonglong2*)(lut + (pr & 0xFFu) * 8));
        fma8(B0, B1, w0, w1, (const ulonglong2*)(lut + (pr >> 8) * 8));
    }
}

// Compact nonzero pair-bytes of hp[0..127] into ascending-k list; returns count.
__device__ __forceinline__ int build_list(const u16* __restrict__ hp, u32* list,
                                          int lane) {
    int base = 0;
#pragma unroll
    for (int c = 0; c < 4; c++) {
        int k = c * 32 + lane;
        unsigned pr = hp[k];
        unsigned m = __ballot_sync(0xffffffffu, pr != 0);
        if (pr) {
            int pos = __popc(m & ((1u << lane) - 1));
            list[base + pos] = (u32)k | (pr << 16);
        }
        base += __popc(m);
    }
    return base;
}

// Butterfly-reduce 8 floats across the warp.
__device__ __forceinline__ void wred8(float* p) {
#pragma unroll
    for (int off = 16; off > 0; off >>= 1) {
#pragma unroll
        for (int t = 0; t < Tn; t++)
            p[t] += __shfl_xor_sync(0xffffffffu, p[t], off);
    }
}

// LN + residual + LIF for one row; returns 4 spike bytes.
__device__ __forceinline__ void ln_lif_row(ull* u0, ull* u1, const float* cb,
                                           unsigned q0, unsigned q1, unsigned q2,
                                           unsigned q3, int lane, unsigned* nout) {
    float p[Tn];
#pragma unroll
    for (int t = 0; t < Tn; t++)
        p[t] = f2lo(u0[t]) + f2hi(u0[t]) + f2lo(u1[t]) + f2hi(u1[t]);
    wred8(p);
    float mu[Tn];
#pragma unroll
    for (int t = 0; t < Tn; t++) mu[t] = p[t] * (1.0f / 128.0f);
#pragma unroll
    for (int t = 0; t < Tn; t++) {
        float a = f2lo(u0[t]) - mu[t];
        float b = f2hi(u0[t]) - mu[t];
        float c = f2lo(u1[t]) - mu[t];
        float d = f2hi(u1[t]) - mu[t];
        p[t] = a * a + b * b + c * c + d * d;
    }
    wred8(p);
    const float g0 = cb[128 + lane],      g1 = cb[128 + lane + 64];
    const float g2 = cb[128 + lane + 32], g3 = cb[128 + lane + 96];
    const float e0 = cb[256 + lane],      e1 = cb[256 + lane + 64];
    const float e2 = cb[256 + lane + 32], e3 = cb[256 + lane + 96];
    float v0 = 0.f, v1 = 0.f, v2 = 0.f, v3 = 0.f;
    unsigned n0 = 0, n1 = 0, n2 = 0, n3 = 0;
#pragma unroll
    for (int t = 0; t < Tn; t++) {
        float rs = rsqrtf(p[t] * (1.0f / 128.0f) + 1e-5f);
        float y0 = (f2lo(u0[t]) - mu[t]) * rs * g0 + e0 + (float)((q0 >> t) & 1);
        float y1 = (f2hi(u0[t]) - mu[t]) * rs * g1 + e1 + (float)((q1 >> t) & 1);
        float y2 = (f2lo(u1[t]) - mu[t]) * rs * g2 + e2 + (float)((q2 >> t) & 1);
        float y3 = (f2hi(u1[t]) - mu[t]) * rs * g3 + e3 + (float)((q3 >> t) & 1);
        v0 += (y0 - v0) * 0.5f; if (v0 >= 1.f) { n0 |= 1u << t; v0 = 0.f; }
        v1 += (y1 - v1) * 0.5f; if (v1 >= 1.f) { n1 |= 1u << t; v1 = 0.f; }
        v2 += (y2 - v2) * 0.5f; if (v2 >= 1.f) { n2 |= 1u << t; v2 = 0.f; }
        v3 += (y3 - v3) * 0.5f; if (v3 >= 1.f) { n3 |= 1u << t; v3 = 0.f; }
    }
    nout[0] = n0; nout[1] = n1; nout[2] = n2; nout[3] = n3;
}

// Plain LIF (no LN/residual) for phase 1.
__device__ __forceinline__ void lif_row(ull* u0, ull* u1, unsigned* nout) {
    float v0 = 0.f, v1 = 0.f, v2 = 0.f, v3 = 0.f;
    unsigned n0 = 0, n1 = 0, n2 = 0, n3 = 0;
#pragma unroll
    for (int t = 0; t < Tn; t++) {
        float a = f2lo(u0[t]), b = f2hi(u0[t]);
        float c = f2lo(u1[t]), d = f2hi(u1[t]);
        v0 += (a - v0) * 0.5f; if (v0 >= 1.f) { n0 |= 1u << t; v0 = 0.f; }
        v1 += (b - v1) * 0.5f; if (v1 >= 1.f) { n1 |= 1u << t; v1 = 0.f; }
        v2 += (c - v2) * 0.5f; if (v2 >= 1.f) { n2 |= 1u << t; v2 = 0.f; }
        v3 += (d - v3) * 0.5f; if (v3 >= 1.f) { n3 |= 1u << t; v3 = 0.f; }
    }
    nout[0] = n0; nout[1] = n1; nout[2] = n2; nout[3] = n3;
}

__device__ __forceinline__ void store_pair(u16* hout, int warp, int lane,
                                           const unsigned* nA, const unsigned* nB) {
    u16* hp = hout + warp * Hn;
    hp[lane]      = (u16)(nA[0] | (nB[0] << 8));
    hp[lane + 64] = (u16)(nA[1] | (nB[1] << 8));
    hp[lane + 32] = (u16)(nA[2] | (nB[2] << 8));
    hp[lane + 96] = (u16)(nA[3] | (nB[3] << 8));
}

// One MS_ResBlock for the warp's row pair (branch-free list GEMM).
__device__ __forceinline__ void resblock_list(const ull* __restrict__ wg,
                                              const float* __restrict__ cb,
                                              const ull* __restrict__ lut,
                                              const u16* __restrict__ hin,
                                              u16* __restrict__ hout,
                                              const u32* __restrict__ list, int nnz,
                                              int warp, int lane) {
    const ull bi0 = pk(cb[lane], cb[lane + 64]);
    const ull bi1 = pk(cb[lane + 32], cb[lane + 96]);
    ull A0[Tn], A1[Tn], B0[Tn], B1[Tn];
#pragma unroll
    for (int t = 0; t < Tn; t++) { A0[t] = bi0; A1[t] = bi1; B0[t] = bi0; B1[t] = bi1; }
    gemm_list(wg, list, nnz, lut, lane, A0, A1, B0, B1);

    const u16* hp = hin + warp * Hn;
    unsigned p0 = hp[lane], p1 = hp[lane + 64], p2 = hp[lane + 32], p3 = hp[lane + 96];
    unsigned nA[4], nB[4];
    ln_lif_row(A0, A1, cb, p0 & 0xFFu, p1 & 0xFFu, p2 & 0xFFu, p3 & 0xFFu, lane, nA);
    ln_lif_row(B0, B1, cb, p0 >> 8, p1 >> 8, p2 >> 8, p3 >> 8, lane, nB);
    store_pair(hout, warp, lane, nA, nB);
    __syncwarp();
}

__global__ __launch_bounds__(BLOCK, 2) void snn_kernel(
    const float* __restrict__ x, const float* __restrict__ enc,
    const float* __restrict__ b_in, const float* __restrict__ b_r1,
    const float* __restrict__ g_r1, const float* __restrict__ be_r1,
    const float* __restrict__ b_r2, const float* __restrict__ g_r2,
    const float* __restrict__ be_r2, const float* __restrict__ W_out,
    const float* __restrict__ b_out, float* __restrict__ out) {
    __shared__ u16 sIN[8 * Sn];
    __shared__ u16 hA[8 * Hn];
    __shared__ u16 hB[8 * Hn];
    __shared__ u32 klist[8 * Hn];  // per-warp compacted k-list
    __shared__ float wout[Hn * An];
    __shared__ float bout[32];
    __shared__ float cb_in[128];
    __shared__ float cb_r1[384];
    __shared__ float cb_r2[384];
    __shared__ ull lut[256 * 8];

    const int b0 = blockIdx.x * RPB;
    const int tid = threadIdx.x;
    const int warp = tid >> 5;
    const int lane = tid & 31;

    // ---- Phase 0: LUT, encode, constants. One block barrier. ----
    for (int i = tid; i < 256 * 8; i += BLOCK) {
        int byte = i >> 3, t = i & 7;
        unsigned u = ((byte >> t) & 1) ? 0x3F800000u : 0u;
        lut[i] = ((ull)u << 32) | u;
    }
    for (int i = tid; i < 8 * 64; i += BLOCK) {
        int w = i >> 6;
        int s4 = (i & 63) * 4;
        int bA = b0 + 2 * w, bB = bA + 1;
        float4 xA = *(const float4*)(x + (size_t)bA * Sn + s4);
        float4 xB = *(const float4*)(x + (size_t)bB * Sn + s4);
        unsigned byA0 = 0, byA1 = 0, byA2 = 0, byA3 = 0;
        unsigned byB0 = 0, byB1 = 0, byB2 = 0, byB3 = 0;
#pragma unroll
        for (int t = 0; t < Tn; t++) {
            float4 eA = *(const float4*)(enc + ((size_t)t * Bn + bA) * Sn + s4);
            float4 eB = *(const float4*)(enc + ((size_t)t * Bn + bB) * Sn + s4);
            unsigned bit = 1u << t;
            if (eA.x <= xA.x) byA0 |= bit;
            if (eA.y <= xA.y) byA1 |= bit;
            if (eA.z <= xA.z) byA2 |= bit;
            if (eA.w <= xA.w) byA3 |= bit;
            if (eB.x <= xB.x) byB0 |= bit;
            if (eB.y <= xB.y) byB1 |= bit;
            if (eB.z <= xB.z) byB2 |= bit;
            if (eB.w <= xB.w) byB3 |= bit;
        }
        ull packed = (ull)(byA0 | (byB0 << 8)) | ((ull)(byA1 | (byB1 << 8)) << 16) |
                     ((ull)(byA2 | (byB2 << 8)) << 32) | ((ull)(byA3 | (byB3 << 8)) << 48);
        *(ull*)(sIN + w * Sn + s4) = packed;
    }
    for (int i = tid; i < Hn; i += BLOCK) {
        cb_in[i] = b_in[i];
        cb_r1[i] = b_r1[i]; cb_r1[128 + i] = g_r1[i]; cb_r1[256 + i] = be_r1[i];
        cb_r2[i] = b_r2[i]; cb_r2[128 + i] = g_r2[i]; cb_r2[256 + i] = be_r2[i];
    }
    for (int i = tid; i < Hn * An; i += BLOCK) wout[i] = W_out[i];
    if (tid < An) bout[tid] = b_out[tid];
    __syncthreads();

    // ---- Phase 1: dense GEMM1 + LIF -> hA (warp-independent) ----
    {
        const ull bi0 = pk(cb_in[lane], cb_in[lane + 64]);
        const ull bi1 = pk(cb_in[lane + 32], cb_in[lane + 96]);
        ull A0[Tn], A1[Tn], B0[Tn], B1[Tn];
#pragma unroll
        for (int t = 0; t < Tn; t++) { A0[t] = bi0; A1[t] = bi1; B0[t] = bi0; B1[t] = bi1; }
        gemm_dense<Sn>(g_Wpk_in, sIN + warp * Sn, lut, lane, A0, A1, B0, B1);
        unsigned nA[4], nB[4];
        lif_row(A0, A1, nA);
        lif_row(B0, B1, nB);
        store_pair(hA, warp, lane, nA, nB);
        __syncwarp();
    }

    // ---- Phases 2-3: ResBlocks over compacted lists (warp-independent) ----
    u32* mylist = klist + warp * Hn;
    {
        int nnz = build_list(hA + warp * Hn, mylist, lane);
        __syncwarp();
        resblock_list(g_Wpk_r1, cb_r1, lut, hA, hB, mylist, nnz, warp, lane);
    }
    {
        int nnz = build_list(hB + warp * Hn, mylist, lane);
        __syncwarp();
        resblock_list(g_Wpk_r2, cb_r2, lut, hB, hA, mylist, nnz, warp, lane);
    }
    __syncthreads();

    // ---- Phase 4: readout GEMM (H=128 -> A=18) + non-spiking LIF + time mean ----
    const float WGT[Tn] = {255.f / 2048.f, 127.f / 1024.f, 63.f / 512.f, 31.f / 256.f,
                           15.f / 128.f,   7.f / 64.f,     3.f / 32.f,   1.f / 16.f};
    const unsigned char* hby = (const unsigned char*)hA;
    for (int task = tid; task < RPB * An; task += BLOCK) {
        int r = task / An;
        int a = task - r * An;
        float acc[Tn] = {0.f, 0.f, 0.f, 0.f, 0.f, 0.f, 0.f, 0.f};
        const unsigned char* hp = hby + (r >> 1) * 256 + (r & 1);
        for (int h = 0; h < Hn; h++) {
            unsigned byte = hp[h * 2];
            float w = wout[h * An + a];
#pragma unroll
            for (int t = 0; t < Tn; t++)
                if (byte & (1u << t)) acc[t] += w;
        }
        float bo = bout[a];
        float o = 0.f;
#pragma unroll
        for (int t = 0; t < Tn; t++) o += WGT[t] * (acc[t] + bo);
        out[(size_t)(b0 + r) * An + a] = o;
    }
}

extern "C" void kernel_launch(void* const* d_in, const int* in_sizes, int n_in,
                              void* d_out, int out_size) {
    const float* x     = (const float*)d_in[0];
    const float* enc   = (const float*)d_in[1];
    const float* W_in  = (const float*)d_in[2];
    const float* b_in  = (const float*)d_in[3];
    const float* W_r1  = (const float*)d_in[4];
    const float* b_r1  = (const float*)d_in[5];
    const float* g_r1  = (const float*)d_in[6];
    const float* be_r1 = (const float*)d_in[7];
    const float* W_r2  = (const float*)d_in[8];
    const float* b_r2  = (const float*)d_in[9];
    const float* g_r2  = (const float*)d_in[10];
    const float* be_r2 = (const float*)d_in[11];
    const float* W_out = (const float*)d_in[12];
    const float* b_out = (const float*)d_in[13];
    float* out = (float*)d_out;

    ull *Wp_in, *Wp_r1, *Wp_r2;
    cudaGetSymbolAddress((void**)&Wp_in, g_Wpk_in);
    cudaGetSymbolAddress((void**)&Wp_r1, g_Wpk_r1);
    cudaGetSymbolAddress((void**)&Wp_r2, g_Wpk_r2);

    pack_kernel<<<(Sn * 64 + 255) / 256, 256>>>(W_in, Wp_in, Sn);
    pack_kernel<<<(Hn * 64 + 255) / 256, 256>>>(W_r1, Wp_r1, Hn);
    pack_kernel<<<(Hn * 64 + 255) / 256, 256>>>(W_r2, Wp_r2, Hn);
    snn_kernel<<<GRID, BLOCK>>>(x, enc, b_in, b_r1, g_r1, be_r1, b_r2, g_r2, be_r2,
                                W_out, b_out, out);
}